// round 8
// baseline (speedup 1.0000x reference)
#include <cuda_runtime.h>
#include <cuda_bf16.h>
#include <cstdint>

// ---------------------------------------------------------------------------
// Problem constants
#define NRED   100000
#define TT     32
#define KFEAT  512
#define THRESH 10.0f
#define KWTA   16

// GEMM tiling: 74 k-splits x 4 m-tiles = 296 CTAs (2 CTAs/SM)
#define SPLITS 74
#define KTILE  64
#define NT     22
#define CHUNK  (KTILE * NT)        // 1408
#define KPAD   (SPLITS * CHUNK)    // 104192
#define MTILE  128

#define SM_A    0
#define SM_ASTG 32768
#define SM_B    (2 * SM_ASTG)      // 65536
#define SM_BSTG 8192
#define SMEMB   (SM_B + 2 * SM_BSTG)   // 81920

// Device scratch (static — no dynamic allocation allowed)
__device__ __align__(128) __nv_bfloat16 g_B[(size_t)64 * KPAD];  // 13.3MB
__device__ float g_partial[SPLITS * TT * KFEAT];
__device__ float g_dot[TT * KFEAT];                // [t][feat]
__device__ float g_tot[KFEAT];
__device__ int   g_cntp[8 * KFEAT];                // partial rank counts

// ---------------------------------------------------------------------------
__device__ __forceinline__ uint32_t smem_u32(const void* p) {
    uint32_t a;
    asm("{ .reg .u64 t; cvta.to.shared.u64 t, %1; cvt.u32.u64 %0, t; }"
        : "=r"(a) : "l"(p));
    return a;
}
__device__ __forceinline__ uint32_t sw128(uint32_t off) {
    return off ^ ((off >> 3) & 0x70);
}
__device__ __forceinline__ uint32_t packbf(__nv_bfloat16 a, __nv_bfloat16 b) {
    __nv_bfloat162 v; v.x = a; v.y = b;
    return *reinterpret_cast<uint32_t*>(&v);
}
__device__ __forceinline__ void split2(float x, __nv_bfloat16& h, __nv_bfloat16& l) {
    h = __float2bfloat16(x);
    l = __float2bfloat16(x - __bfloat162float(h));
}
__device__ __forceinline__ void cpasync16(uint32_t dst, const void* src) {
    asm volatile("cp.async.cg.shared.global [%0], [%1], 16;"
                 :: "r"(dst), "l"(src) : "memory");
}
__device__ __forceinline__ void cpasync_commit() {
    asm volatile("cp.async.commit_group;" ::: "memory");
}
__device__ __forceinline__ void cpasync_wait0() {
    asm volatile("cp.async.wait_group 0;" ::: "memory");
}
#define LDSM4(R, ADDR)                                                        \
    asm volatile("ldmatrix.sync.aligned.m8n8.x4.shared.b16 {%0,%1,%2,%3}, [%4];" \
                 : "=r"((R)[0]), "=r"((R)[1]), "=r"((R)[2]), "=r"((R)[3])     \
                 : "r"(ADDR))
#define MMA16816(D, A, B0, B1)                                                \
    asm volatile("mma.sync.aligned.m16n8k16.row.col.f32.bf16.bf16.f32 "       \
                 "{%0,%1,%2,%3}, {%4,%5,%6,%7}, {%8,%9}, {%0,%1,%2,%3};"      \
                 : "+f"((D)[0]), "+f"((D)[1]), "+f"((D)[2]), "+f"((D)[3])     \
                 : "r"((A)[0]), "r"((A)[1]), "r"((A)[2]), "r"((A)[3]),        \
                   "r"(B0), "r"(B1))

// ---------------------------------------------------------------------------
// Split rec_field into bf16 hi/lo, zero-padded to KPAD
// ---------------------------------------------------------------------------
__global__ void __launch_bounds__(256)
conv_kernel(const float* __restrict__ R) {
    const int k4 = (blockIdx.x * 256 + threadIdx.x) * 4;
    if (k4 >= KPAD) return;
    const bool ok = (k4 < NRED);
#pragma unroll 4
    for (int t = 0; t < TT; t++) {
        float4 x = ok ? *(const float4*)(R + (size_t)t * NRED + k4)
                      : make_float4(0.f, 0.f, 0.f, 0.f);
        __nv_bfloat16 h0,h1,h2,h3,l0,l1,l2,l3;
        split2(x.x, h0, l0); split2(x.y, h1, l1);
        split2(x.z, h2, l2); split2(x.w, h3, l3);
        *(uint2*)(g_B + (size_t)t * KPAD + k4)        = make_uint2(packbf(h0,h1), packbf(h2,h3));
        *(uint2*)(g_B + (size_t)(t + 32) * KPAD + k4) = make_uint2(packbf(l0,l1), packbf(l2,l3));
    }
}

// ---------------------------------------------------------------------------
// GEMM: bf16 3-term split (unchanged from R7 — passing at rel_err 0.0)
// ---------------------------------------------------------------------------
__global__ void __launch_bounds__(256, 2)
gemm_kernel(const float* __restrict__ W) {
    extern __shared__ char smem[];
    const uint32_t sb = smem_u32(smem);

    const int tid  = threadIdx.x;
    const int lane = tid & 31;
    const int wrp  = tid >> 5;
    const int q    = wrp & 3;
    const int grp  = wrp >> 2;
    const int split = blockIdx.x;
    const int m0    = blockIdx.y * MTILE;
    const int kbase = split * CHUNK;

    const int row_off = lane >> 4;
    const int kq      = lane & 15;
    const int brow = tid >> 2;
    const uint32_t bcol = (uint32_t)(tid & 3) * 32;

    const int s0 = 2 * q, s1 = 2 * q + 1;
    const int arow0 = s0 * 16 + (lane & 7) + ((lane >> 3) & 1) * 8;
    const int arow1 = s1 * 16 + (lane & 7) + ((lane >> 3) & 1) * 8;
    const uint32_t a_kb0 = ((lane >> 4) & 1) * 16;
    const uint32_t a_off0 = (uint32_t)arow0 * 128;
    const uint32_t a_off1 = (uint32_t)arow1 * 128;
    const uint32_t a_xr0  = (uint32_t)(arow0 & 7) << 4;
    const uint32_t a_xr1  = (uint32_t)(arow1 & 7) << 4;
    const int browl = (lane & 7) + ((lane >> 4) & 1) * 8;
    const uint32_t b_rb  = (uint32_t)browl * 128 + (uint32_t)grp * 4096;
    const uint32_t b_xr  = (uint32_t)(lane & 7) << 4;
    const uint32_t b_kb0 = ((lane >> 3) & 1) * 16;

    float d[2][4][4];
#pragma unroll
    for (int s = 0; s < 2; s++)
#pragma unroll
        for (int i = 0; i < 4; i++)
#pragma unroll
            for (int j = 0; j < 4; j++) d[s][i][j] = 0.0f;

    float4 wr[8];
    const float4 z4 = make_float4(0.f, 0.f, 0.f, 0.f);

#define LOAD_W(TL) do {                                                      \
    const int kp_ = kbase + (TL) * KTILE + kq * 4;                           \
    const bool ok_ = (kp_ < NRED);                                           \
    const float* wp_ = W + (size_t)(m0 + wrp * 2 + row_off) * NRED + kp_;    \
    _Pragma("unroll")                                                        \
    for (int i = 0; i < 8; i++)                                              \
        wr[i] = ok_ ? *(const float4*)(wp_ + (size_t)16 * i * NRED) : z4;    \
} while (0)

#define ASYNC_B(TL, BUF) do {                                                \
    const __nv_bfloat16* src_ = g_B + (size_t)brow * KPAD                    \
                              + (kbase + (TL) * KTILE) + (bcol >> 1);        \
    const uint32_t db_ = sb + SM_B + (BUF) * SM_BSTG;                        \
    const uint32_t bo_ = (uint32_t)brow * 128 + bcol;                        \
    cpasync16(db_ + sw128(bo_),      src_);                                  \
    cpasync16(db_ + sw128(bo_ + 16), src_ + 8);                              \
    cpasync_commit();                                                        \
} while (0)

#define STS_A(BUF) do {                                                      \
    char* ab_ = smem + SM_A + (BUF) * SM_ASTG;                               \
    _Pragma("unroll")                                                        \
    for (int i = 0; i < 8; i++) {                                            \
        const int row_ = i * 16 + wrp * 2 + row_off;                         \
        const uint32_t sw_ = sw128((uint32_t)row_ * 128 + kq * 8);           \
        float4 f_ = wr[i];                                                   \
        __nv_bfloat16 h0,h1,h2,h3,l0,l1,l2,l3;                               \
        split2(f_.x, h0, l0); split2(f_.y, h1, l1);                          \
        split2(f_.z, h2, l2); split2(f_.w, h3, l3);                          \
        *(uint2*)(ab_ + sw_)         = make_uint2(packbf(h0,h1), packbf(h2,h3)); \
        *(uint2*)(ab_ + sw_ + 16384) = make_uint2(packbf(l0,l1), packbf(l2,l3)); \
    }                                                                        \
} while (0)

#define COMPUTE(BUF) do {                                                    \
    const uint32_t sa_ = sb + SM_A + (BUF) * SM_ASTG;                        \
    const uint32_t sB_ = sb + SM_B + (BUF) * SM_BSTG;                        \
    _Pragma("unroll")                                                        \
    for (int ks = 0; ks < 4; ks++) {                                         \
        uint32_t ah0[4], ah1[4], bf[2][4];                                   \
        const uint32_t kb_ = (uint32_t)(ks * 32) + a_kb0;                    \
        LDSM4(ah0, sa_ + a_off0 + (kb_ ^ a_xr0));                            \
        LDSM4(ah1, sa_ + a_off1 + (kb_ ^ a_xr1));                            \
        const uint32_t bkb_ = ((uint32_t)(ks * 32) + b_kb0) ^ b_xr;          \
        LDSM4(bf[0], sB_ + b_rb + bkb_);                                     \
        LDSM4(bf[1], sB_ + 2048 + b_rb + bkb_);                              \
        MMA16816(d[0][0], ah0, bf[0][0], bf[0][1]);                          \
        MMA16816(d[0][1], ah0, bf[0][2], bf[0][3]);                          \
        MMA16816(d[0][2], ah0, bf[1][0], bf[1][1]);                          \
        MMA16816(d[0][3], ah0, bf[1][2], bf[1][3]);                          \
        MMA16816(d[1][0], ah1, bf[0][0], bf[0][1]);                          \
        MMA16816(d[1][1], ah1, bf[0][2], bf[0][3]);                          \
        MMA16816(d[1][2], ah1, bf[1][0], bf[1][1]);                          \
        MMA16816(d[1][3], ah1, bf[1][2], bf[1][3]);                          \
        if (grp == 0) {                                                      \
            uint32_t al0[4], al1[4];                                         \
            LDSM4(al0, sa_ + 16384 + a_off0 + (kb_ ^ a_xr0));                \
            LDSM4(al1, sa_ + 16384 + a_off1 + (kb_ ^ a_xr1));                \
            MMA16816(d[0][0], al0, bf[0][0], bf[0][1]);                      \
            MMA16816(d[0][1], al0, bf[0][2], bf[0][3]);                      \
            MMA16816(d[0][2], al0, bf[1][0], bf[1][1]);                      \
            MMA16816(d[0][3], al0, bf[1][2], bf[1][3]);                      \
            MMA16816(d[1][0], al1, bf[0][0], bf[0][1]);                      \
            MMA16816(d[1][1], al1, bf[0][2], bf[0][3]);                      \
            MMA16816(d[1][2], al1, bf[1][0], bf[1][1]);                      \
            MMA16816(d[1][3], al1, bf[1][2], bf[1][3]);                      \
        }                                                                    \
    }                                                                        \
} while (0)

    ASYNC_B(0, 0);
    LOAD_W(0);
    STS_A(0);
    cpasync_wait0();
    __syncthreads();

    for (int tl = 0; tl < NT; tl++) {
        if (tl + 1 < NT) {
            ASYNC_B(tl + 1, (tl + 1) & 1);
            LOAD_W(tl + 1);
        }
        COMPUTE(tl & 1);
        if (tl + 1 < NT) {
            STS_A((tl + 1) & 1);
            cpasync_wait0();
            __syncthreads();
        }
    }

    __syncthreads();
    float* es = (float*)smem;
    const int eidx = (q * 32 + lane) * 33;
    if (grp == 1) {
#pragma unroll
        for (int s = 0; s < 2; s++)
#pragma unroll
            for (int i = 0; i < 4; i++)
#pragma unroll
                for (int j = 0; j < 4; j++)
                    es[eidx + s * 16 + i * 4 + j] = d[s][i][j];
    }
    __syncthreads();
    if (grp == 0) {
        float* gp = g_partial + (size_t)split * (TT * KFEAT) + m0;
        const int rbase = lane >> 2;
        const int c0 = (lane & 3) * 2;
#pragma unroll
        for (int s = 0; s < 2; s++) {
            const int feat = (2 * q + s) * 16 + rbase;
#pragma unroll
            for (int nt = 0; nt < 4; nt++) {
                const int t0 = nt * 8 + c0;
                float v0 = d[s][nt][0] + es[eidx + s * 16 + nt * 4 + 0];
                float v1 = d[s][nt][1] + es[eidx + s * 16 + nt * 4 + 1];
                float v2 = d[s][nt][2] + es[eidx + s * 16 + nt * 4 + 2];
                float v3 = d[s][nt][3] + es[eidx + s * 16 + nt * 4 + 3];
                gp[(size_t)t0 * KFEAT + feat]           = v0;
                gp[(size_t)(t0 + 1) * KFEAT + feat]     = v1;
                gp[(size_t)t0 * KFEAT + feat + 8]       = v2;
                gp[(size_t)(t0 + 1) * KFEAT + feat + 8] = v3;
            }
        }
    }
}

// ---------------------------------------------------------------------------
// Reduce partials across splits: g_dot[t][feat]
// ---------------------------------------------------------------------------
__global__ void __launch_bounds__(256)
reduce_kernel() {
    const int j = blockIdx.x * 256 + threadIdx.x;
    float s = 0.0f;
#pragma unroll 8
    for (int sp = 0; sp < SPLITS; sp++) s += g_partial[sp * (TT * KFEAT) + j];
    g_dot[j] = s;
}

// ---------------------------------------------------------------------------
// Totals (exact reference math): 1 block x 512
// ---------------------------------------------------------------------------
__global__ void __launch_bounds__(512, 1)
totals_kernel() {
    __shared__ float red_s[16];
    __shared__ float v_s;
    const int k = threadIdx.x;

    int nspk = 0;
#pragma unroll
    for (int t = 0; t < TT; t++) {
        float dd = g_dot[t * KFEAT + k];
        nspk += (dd > THRESH) ? 1 : 0;
    }
    int first = TT - nspk;
    if (first > TT - 1) first = TT - 1;
    if (first < 0) first = 0;
    float dv = g_dot[first * KFEAT + k];
    float value = (dv > THRESH) ? dv : 0.0f;
    float sval = (nspk > 0) ? value : 0.0f;

    float m = sval;
#pragma unroll
    for (int o = 16; o > 0; o >>= 1)
        m = fmaxf(m, __shfl_xor_sync(0xffffffffu, m, o));
    if ((k & 31) == 0) red_s[k >> 5] = m;
    __syncthreads();
    if (k == 0) {
        float mm = red_s[0];
#pragma unroll
        for (int i = 1; i < 16; i++) mm = fmaxf(mm, red_s[i]);
        v_s = mm * (float)TT;
    }
    __syncthreads();

    const float fns = (float)nspk;
    g_tot[k] = fns * value + fns * v_s;
}

// ---------------------------------------------------------------------------
// Partial rank counts: 8 blocks x 512. Block b counts j in [64b, 64b+64).
// Rank-count == sequential suppressive argmax (first-index tie-break).
// ---------------------------------------------------------------------------
__global__ void __launch_bounds__(512, 1)
count_kernel() {
    __shared__ float seg[64];
    const int k = threadIdx.x;
    const int b = blockIdx.x;
    const int jbase = b * 64;
    if (k < 64) seg[k] = g_tot[jbase + k];
    const float total = g_tot[k];
    __syncthreads();

    int cnt = 0;
#pragma unroll
    for (int jj = 0; jj < 16; jj++) {
        float4 tv = *(const float4*)(seg + jj * 4);
        const int j0 = jbase + jj * 4;
        cnt += ((tv.x > total) || (tv.x == total && (j0 + 0) < k)) ? 1 : 0;
        cnt += ((tv.y > total) || (tv.y == total && (j0 + 1) < k)) ? 1 : 0;
        cnt += ((tv.z > total) || (tv.z == total && (j0 + 2) < k)) ? 1 : 0;
        cnt += ((tv.w > total) || (tv.w == total && (j0 + 3) < k)) ? 1 : 0;
    }
    g_cntp[b * KFEAT + k] = cnt;
}

// ---------------------------------------------------------------------------
// Output: 1 block x 512
// ---------------------------------------------------------------------------
__global__ void __launch_bounds__(512, 1)
output_kernel(float* __restrict__ out) {
    const int k = threadIdx.x;
    int cnt = 0;
#pragma unroll
    for (int b = 0; b < 8; b++) cnt += g_cntp[b * KFEAT + k];
    const float total = g_tot[k];
    const bool win = (total > 0.0f) && (cnt < KWTA);
#pragma unroll
    for (int t = 0; t < TT; t++) {
        float dd = g_dot[t * KFEAT + k];
        out[t * KFEAT + k] = (win && dd > THRESH) ? 1.0f : 0.0f;
    }
}

// ---------------------------------------------------------------------------
extern "C" void kernel_launch(void* const* d_in, const int* in_sizes, int n_in,
                              void* d_out, int out_size) {
    const float* a = (const float*)d_in[0];
    const float* b = (const float*)d_in[1];
    const float* rec = a;
    const float* wgt = b;
    if (in_sizes[0] > in_sizes[1]) { rec = b; wgt = a; }

    cudaFuncSetAttribute(gemm_kernel,
                         cudaFuncAttributeMaxDynamicSharedMemorySize, SMEMB);

    conv_kernel<<<(KPAD / 4 + 255) / 256, 256>>>(rec);
    dim3 grid(SPLITS, 4);
    gemm_kernel<<<grid, 256, SMEMB>>>(wgt);
    reduce_kernel<<<(TT * KFEAT) / 256, 256>>>();
    totals_kernel<<<1, 512>>>();
    count_kernel<<<8, 512>>>();
    output_kernel<<<1, 512>>>((float*)d_out);
}